// round 14
// baseline (speedup 1.0000x reference)
#include <cuda_runtime.h>
#include <cuda_bf16.h>
#include <math.h>
#include <stdint.h>

// ---------------------------------------------------------------------------
// EfficientFormer self-attention. GEMMs on tensor cores via mma.sync bf16
// (3-way hi/lo split, fp32 accumulate). tcgen05 is unavailable under this
// harness's compute_103 virtual target; mma.sync m16n8k16 compiles fine.
//   GEMM1: qkv[M,1536] = hidden[M,448] @ qkv_w^T + qkv_b   (K'=1344 bf16)
//   attn : per (b,h) 49x49 attention, fp32; emits bf16-split ctx directly
//   GEMM2: out[M,448]  = ctx[M,1024]  @ proj_w^T + proj_b  (K'=3072 bf16)
// R9 profile: tensor=52.7%, L1=78.2% -> smem-bound. This round: warp tile
// 64x64 (2.1x fewer LDSM bytes/MMA), 3-stage cp.async pipeline.
// ---------------------------------------------------------------------------

#define M_TOTAL   (2048 * 49)
#define SEQ       49
#define NHEADS    8
#define QKV_COLS  1536
#define CTX_COLS  1024
#define OUT_COLS  448
#define IN_COLS   448
#define K3_1      (3 * IN_COLS)    // 1344
#define K3_2      (3 * CTX_COLS)   // 3072

// Scratch (__device__ globals; cudaMalloc forbidden).
__device__ __align__(256) float         g_qkv[(size_t)M_TOTAL * QKV_COLS];  // 616 MB
__device__ __align__(256) __nv_bfloat16 g_A1 [(size_t)M_TOTAL * K3_1];      // 270 MB
__device__ __align__(256) __nv_bfloat16 g_B1 [(size_t)QKV_COLS * K3_1];
__device__ __align__(256) __nv_bfloat16 g_A2 [(size_t)M_TOTAL * K3_2];      // 616 MB
__device__ __align__(256) __nv_bfloat16 g_B2 [(size_t)OUT_COLS * K3_2];

// ============================ PTX helpers ==================================
__device__ __forceinline__ uint32_t smem_u32(const void* p) {
    uint32_t a;
    asm("{ .reg .u64 t; cvta.to.shared.u64 t, %1; cvt.u32.u64 %0, t; }"
        : "=r"(a) : "l"(p));
    return a;
}
#define CP16(s, g) \
    asm volatile("cp.async.ca.shared.global [%0], [%1], 16;" :: "r"(s), "l"(g) : "memory")
#define CP_COMMIT() asm volatile("cp.async.commit_group;" ::: "memory")
#define CP_WAIT(n)  asm volatile("cp.async.wait_group %0;" :: "n"(n) : "memory")

__device__ __forceinline__ void ldm_x4(uint32_t* r, uint32_t addr) {
    asm volatile("ldmatrix.sync.aligned.m8n8.x4.shared.b16 {%0,%1,%2,%3}, [%4];"
                 : "=r"(r[0]), "=r"(r[1]), "=r"(r[2]), "=r"(r[3]) : "r"(addr));
}
__device__ __forceinline__ void mma_bf16(float* c, const uint32_t* a,
                                         uint32_t b0, uint32_t b1) {
    asm volatile(
        "mma.sync.aligned.m16n8k16.row.col.f32.bf16.bf16.f32 "
        "{%0,%1,%2,%3}, {%4,%5,%6,%7}, {%8,%9}, {%0,%1,%2,%3};"
        : "+f"(c[0]), "+f"(c[1]), "+f"(c[2]), "+f"(c[3])
        : "r"(a[0]), "r"(a[1]), "r"(a[2]), "r"(a[3]), "r"(b0), "r"(b1));
}

// ============================ split kernel =================================
// fp32 [rows,K] -> bf16 [rows,3K].  MODE 0 (A-side): [hi|lo|hi];
//                                   MODE 1 (B-side): [hi|hi|lo].
template<int MODE>
__global__ void split3_kernel(const float* __restrict__ X,
                              __nv_bfloat16* __restrict__ Y,
                              int K, int K3, long long n4)
{
    long long i = (long long)blockIdx.x * blockDim.x + threadIdx.x;
    if (i >= n4) return;
    long long e = i * 4;
    long long row = e / K;
    int col = (int)(e - row * K);
    float4 x = *reinterpret_cast<const float4*>(X + e);

    union { __nv_bfloat16 b[4]; uint2 u; } hi, lo;
    hi.b[0] = __float2bfloat16(x.x); hi.b[1] = __float2bfloat16(x.y);
    hi.b[2] = __float2bfloat16(x.z); hi.b[3] = __float2bfloat16(x.w);
    lo.b[0] = __float2bfloat16(x.x - __bfloat162float(hi.b[0]));
    lo.b[1] = __float2bfloat16(x.y - __bfloat162float(hi.b[1]));
    lo.b[2] = __float2bfloat16(x.z - __bfloat162float(hi.b[2]));
    lo.b[3] = __float2bfloat16(x.w - __bfloat162float(hi.b[3]));

    __nv_bfloat16* yb = Y + row * K3 + col;
    *reinterpret_cast<uint2*>(yb) = hi.u;
    if (MODE == 0) {
        *reinterpret_cast<uint2*>(yb + K)     = lo.u;
        *reinterpret_cast<uint2*>(yb + 2 * K) = hi.u;
    } else {
        *reinterpret_cast<uint2*>(yb + K)     = hi.u;
        *reinterpret_cast<uint2*>(yb + 2 * K) = lo.u;
    }
}

// ============================ mma GEMM =====================================
// C[M,N] = A[M,K3] * B[N,K3]^T + bias[N].  bf16 in, fp32 out.
// 256 thr = 8 warps, warp tile WM x WN, 3-stage cp.async pipeline, dyn smem.
template<int BM, int BN, int WM, int WN>
__global__ __launch_bounds__(256, 1)
void gemm_mma(const __nv_bfloat16* __restrict__ A,
              const __nv_bfloat16* __restrict__ B,
              const float* __restrict__ bias,
              float* __restrict__ C, int N, int K3)
{
    constexpr int NT   = 256;
    constexpr int BK   = 32;
    constexpr int LDK  = BK + 8;           // 80B row stride: ldmatrix bank-clean
    constexpr int ST   = 3;                // pipeline stages
    constexpr int MW   = BM / WM;          // warps along m
    constexpr int MT   = WM / 16;          // 16-row tiles per warp
    constexpr int NF   = WN / 8;           // n8 fragments per warp
    constexpr int NTL  = WN / 16;          // ldmatrix x4 B loads per warp
    constexpr int CA   = BM * (BK / 8) / NT;
    constexpr int CB   = BN * (BK / 8) / NT;
    static_assert(MW * (BN / WN) == 8, "8 warps");
    static_assert(CA >= 1 && CB >= 1, "tile loads");

    extern __shared__ __align__(16) char dyn[];
    __nv_bfloat16* sAp = reinterpret_cast<__nv_bfloat16*>(dyn);
    __nv_bfloat16* sBp = sAp + (size_t)ST * BM * LDK;
    const uint32_t uA = smem_u32(sAp);
    const uint32_t uB = smem_u32(sBp);

    const int tid  = threadIdx.x;
    const int wid  = tid >> 5;
    const int lane = tid & 31;
    const int bm   = blockIdx.y * BM;
    const int bn   = blockIdx.x * BN;
    const int wm   = (wid % MW) * WM;
    const int wn   = (wid / MW) * WN;

    // ldmatrix lane coordinates
    const int sel = lane >> 3, r8 = lane & 7;
    const int ar = wm + (sel & 1) * 8 + r8;      // A: (m8, k8) tile order
    const int ac = (sel >> 1) * 8;
    const int br = wn + (sel >> 1) * 8 + r8;     // B: (k8, n8) tile order
    const int bc = (sel & 1) * 8;

    float acc[MT][NF][4];
#pragma unroll
    for (int i = 0; i < MT; ++i)
#pragma unroll
        for (int j = 0; j < NF; ++j)
#pragma unroll
            for (int q = 0; q < 4; ++q) acc[i][j][q] = 0.f;

    const int NC = K3 / BK;

    auto load_stage = [&](int ci, int s) {
        const size_t k0 = (size_t)ci * BK;
#pragma unroll
        for (int i = 0; i < CA; ++i) {
            int ch = tid + i * NT;
            int rr = ch >> 2;                    // BK/8 = 4 chunks per row
            int cc = (ch & 3) * 8;
            const void* g = A + (size_t)(bm + rr) * K3 + k0 + cc;
            uint32_t sa = uA + (uint32_t)(((s * BM + rr) * LDK + cc) * 2);
            CP16(sa, g);
        }
#pragma unroll
        for (int i = 0; i < CB; ++i) {
            int ch = tid + i * NT;
            int rr = ch >> 2;
            int cc = (ch & 3) * 8;
            const void* g = B + (size_t)(bn + rr) * K3 + k0 + cc;
            uint32_t sb = uB + (uint32_t)(((s * BN + rr) * LDK + cc) * 2);
            CP16(sb, g);
        }
        CP_COMMIT();
    };

    load_stage(0, 0);
    load_stage(1, 1);

    for (int ci = 0; ci < NC; ++ci) {
        const int s = ci % ST;
        if (ci + ST - 1 < NC) CP_WAIT(1);    // chunk ci arrived (in-order groups)
        else                  CP_WAIT(0);    // tail: drain
        __syncthreads();                     // also fences slot reuse (ci-1 done)

        if (ci + ST - 1 < NC) load_stage(ci + ST - 1, (ci + ST - 1) % ST);

#pragma unroll
        for (int ks = 0; ks < BK / 16; ++ks) {
            uint32_t afr[MT][4], bfr[NTL][4];
#pragma unroll
            for (int mt = 0; mt < MT; ++mt)
                ldm_x4(afr[mt], uA + (uint32_t)(((s * BM + ar + mt * 16) * LDK
                                                 + ac + ks * 16) * 2));
#pragma unroll
            for (int nt = 0; nt < NTL; ++nt)
                ldm_x4(bfr[nt], uB + (uint32_t)(((s * BN + br + nt * 16) * LDK
                                                 + bc + ks * 16) * 2));
#pragma unroll
            for (int mt = 0; mt < MT; ++mt)
#pragma unroll
                for (int nf = 0; nf < NF; ++nf) {
                    const uint32_t* bp = bfr[nf >> 1];
                    if (nf & 1) mma_bf16(acc[mt][nf], afr[mt], bp[2], bp[3]);
                    else        mma_bf16(acc[mt][nf], afr[mt], bp[0], bp[1]);
                }
        }
    }

    // Epilogue: bias + store (float2 per fragment row)
    const int g  = lane >> 2;
    const int t2 = (lane & 3) * 2;
#pragma unroll
    for (int mt = 0; mt < MT; ++mt) {
        int row0 = bm + wm + mt * 16 + g;
#pragma unroll
        for (int nf = 0; nf < NF; ++nf) {
            int col = bn + wn + nf * 8 + t2;
            float bx = __ldg(&bias[col]), by = __ldg(&bias[col + 1]);
            float2 v0 = make_float2(acc[mt][nf][0] + bx, acc[mt][nf][1] + by);
            float2 v1 = make_float2(acc[mt][nf][2] + bx, acc[mt][nf][3] + by);
            *reinterpret_cast<float2*>(&C[(size_t)row0 * N + col])       = v0;
            *reinterpret_cast<float2*>(&C[(size_t)(row0 + 8) * N + col]) = v1;
        }
    }
}

// ============================ attention ====================================
// Emits ctx directly as bf16 3-split rows of g_A2: [hi | lo | hi] over K=1024.
__global__ __launch_bounds__(256)
void attn_kernel(const float* __restrict__ qkv,
                 const float* __restrict__ biases,     // [8,49]
                 const int*   __restrict__ bias_idxs,  // [49*49] i32 (or i64 words)
                 __nv_bfloat16* __restrict__ A2)       // [M, 3072]
{
    const int b = blockIdx.x >> 3;
    const int h = blockIdx.x & 7;
    const int tid = threadIdx.x;

    __shared__ __align__(16) float vs[SEQ][128];
    __shared__ __align__(16) float qs[SEQ][33];
    __shared__ __align__(16) float ks[SEQ][33];
    __shared__ __align__(16) float sc[SEQ][SEQ];
    __shared__ __align__(16) float bias_s[SEQ];

    const bool idx64 = (__ldg(&bias_idxs[1]) == 0);

    const float* base = qkv + (size_t)b * (SEQ * QKV_COLS) + h * 192;
    for (int i = tid; i < SEQ * 192; i += 256) {
        int s = i / 192, c = i - s * 192;
        float val = base[(size_t)s * QKV_COLS + c];
        if (c < 32)       qs[s][c]       = val;
        else if (c < 64)  ks[s][c - 32]  = val;
        else              vs[s][c - 64]  = val;
    }
    if (tid < SEQ) bias_s[tid] = biases[h * SEQ + tid];
    __syncthreads();

    const float scale = 0.17677669529663687f;   // 32^-0.5
    for (int idx = tid; idx < SEQ * SEQ; idx += 256) {
        int qi = idx / SEQ, kj = idx - qi * SEQ;
        float acc = 0.f;
#pragma unroll
        for (int d = 0; d < 32; ++d) acc = fmaf(qs[qi][d], ks[kj][d], acc);
        int bidx = idx64 ? __ldg(&bias_idxs[2 * idx]) : __ldg(&bias_idxs[idx]);
        sc[qi][kj] = acc * scale + bias_s[bidx];
    }
    __syncthreads();

    if (tid < SEQ) {
        float m = -3.4e38f;
#pragma unroll 7
        for (int j = 0; j < SEQ; ++j) m = fmaxf(m, sc[tid][j]);
        float sum = 0.f;
        for (int j = 0; j < SEQ; ++j) {
            float e = expf(sc[tid][j] - m);
            sc[tid][j] = e;
            sum += e;
        }
        float inv = 1.f / sum;
        for (int j = 0; j < SEQ; ++j) sc[tid][j] *= inv;
    }
    __syncthreads();

    __nv_bfloat16* obase = A2 + (size_t)(b * SEQ) * K3_2 + h * 128;
    for (int u = tid; u < SEQ * 32; u += 256) {
        int qi = u >> 5;
        int d  = (u & 31) * 4;
        float4 acc = make_float4(0.f, 0.f, 0.f, 0.f);
#pragma unroll
        for (int j = 0; j < SEQ; ++j) {
            float p = sc[qi][j];
            float4 vv = *reinterpret_cast<const float4*>(&vs[j][d]);
            acc.x = fmaf(p, vv.x, acc.x);
            acc.y = fmaf(p, vv.y, acc.y);
            acc.z = fmaf(p, vv.z, acc.z);
            acc.w = fmaf(p, vv.w, acc.w);
        }
        union { __nv_bfloat16 bb[4]; uint2 u2; } hi, lo;
        hi.bb[0] = __float2bfloat16(acc.x); hi.bb[1] = __float2bfloat16(acc.y);
        hi.bb[2] = __float2bfloat16(acc.z); hi.bb[3] = __float2bfloat16(acc.w);
        lo.bb[0] = __float2bfloat16(acc.x - __bfloat162float(hi.bb[0]));
        lo.bb[1] = __float2bfloat16(acc.y - __bfloat162float(hi.bb[1]));
        lo.bb[2] = __float2bfloat16(acc.z - __bfloat162float(hi.bb[2]));
        lo.bb[3] = __float2bfloat16(acc.w - __bfloat162float(hi.bb[3]));
        __nv_bfloat16* orow = obase + (size_t)qi * K3_2 + d;
        *reinterpret_cast<uint2*>(orow)                = hi.u2;   // hi
        *reinterpret_cast<uint2*>(orow + CTX_COLS)     = lo.u2;   // lo
        *reinterpret_cast<uint2*>(orow + 2 * CTX_COLS) = hi.u2;   // hi
    }
}

// ============================ launch =======================================
extern "C" void kernel_launch(void* const* d_in, const int* in_sizes, int n_in,
                              void* d_out, int out_size)
{
    const float* hidden = (const float*)d_in[0];   // [2048,49,448]
    const float* qkv_w  = (const float*)d_in[1];   // [1536,448]
    const float* qkv_b  = (const float*)d_in[2];   // [1536]
    const float* proj_w = (const float*)d_in[3];   // [448,1024]
    const float* proj_b = (const float*)d_in[4];   // [448]
    const float* att_b  = (const float*)d_in[5];   // [8,49]
    const int*   idxs   = (const int*)d_in[6];     // [49,49]
    float* out = (float*)d_out;                    // [2048,49,448] fp32

    float* qkv; __nv_bfloat16 *A1, *B1, *A2, *B2;
    cudaGetSymbolAddress((void**)&qkv, g_qkv);
    cudaGetSymbolAddress((void**)&A1,  g_A1);
    cudaGetSymbolAddress((void**)&B1,  g_B1);
    cudaGetSymbolAddress((void**)&A2,  g_A2);
    cudaGetSymbolAddress((void**)&B2,  g_B2);

    // 3 stages * (BM + BN) rows * 80 B/row
    const int DYN1 = 3 * (128 + 256) * 80;   // 92160
    const int DYN2 = 3 * (256 + 64) * 80;    // 76800
    cudaFuncSetAttribute((const void*)gemm_mma<128, 256, 64, 64>,
                         cudaFuncAttributeMaxDynamicSharedMemorySize, DYN1);
    cudaFuncSetAttribute((const void*)gemm_mma<256, 64, 64, 32>,
                         cudaFuncAttributeMaxDynamicSharedMemorySize, DYN2);

    // splits for GEMM1 inputs (+ proj_w up front)
    {
        long long n4 = (long long)M_TOTAL * IN_COLS / 4;
        split3_kernel<0><<<(unsigned)((n4 + 255) / 256), 256>>>(hidden, A1, IN_COLS, K3_1, n4);
    }
    {
        long long n4 = (long long)QKV_COLS * IN_COLS / 4;
        split3_kernel<1><<<(unsigned)((n4 + 255) / 256), 256>>>(qkv_w, B1, IN_COLS, K3_1, n4);
    }
    {
        long long n4 = (long long)OUT_COLS * CTX_COLS / 4;
        split3_kernel<1><<<(unsigned)((n4 + 255) / 256), 256>>>(proj_w, B2, CTX_COLS, K3_2, n4);
    }

    // GEMM1: qkv = A1 @ B1^T + qkv_b   (M=100352, N=1536, K'=1344)
    {
        dim3 grid(QKV_COLS / 256, M_TOTAL / 128);
        gemm_mma<128, 256, 64, 64><<<grid, 256, DYN1>>>(A1, B1, qkv_b, qkv, QKV_COLS, K3_1);
    }

    // Attention (writes bf16-split ctx into A2)
    attn_kernel<<<2048 * NHEADS, 256>>>(qkv, att_b, idxs, A2);

    // GEMM2: out = A2 @ B2^T + proj_b  (M=100352, N=448, K'=3072)
    {
        dim3 grid(OUT_COLS / 64, M_TOTAL / 256);
        gemm_mma<256, 64, 64, 32><<<grid, 256, DYN2>>>(A2, B2, proj_b, out, OUT_COLS, K3_2);
    }
}

// round 15
// speedup vs baseline: 1.0931x; 1.0931x over previous
#include <cuda_runtime.h>
#include <cuda_bf16.h>
#include <math.h>
#include <stdint.h>

// ---------------------------------------------------------------------------
// EfficientFormer self-attention. GEMMs on tensor cores via mma.sync bf16
// (3-way hi/lo split, fp32 accumulate). tcgen05 unavailable (compute_103
// virtual target); mma.sync m16n8k16 is the tensor path.
// R14 lesson: 8-warp/1-CTA-per-SM is latency-bound at barriers (occ 12%,
// issue 16%). This round: 4-warp CTAs, 2 CTAs/SM (two barrier domains),
// warp tile 64x64 kept, 4-stage cp.async pipeline.
// ---------------------------------------------------------------------------

#define M_TOTAL   (2048 * 49)
#define SEQ       49
#define NHEADS    8
#define QKV_COLS  1536
#define CTX_COLS  1024
#define OUT_COLS  448
#define IN_COLS   448
#define K3_1      (3 * IN_COLS)    // 1344
#define K3_2      (3 * CTX_COLS)   // 3072

// Scratch (__device__ globals; cudaMalloc forbidden).
__device__ __align__(256) float         g_qkv[(size_t)M_TOTAL * QKV_COLS];
__device__ __align__(256) __nv_bfloat16 g_A1 [(size_t)M_TOTAL * K3_1];
__device__ __align__(256) __nv_bfloat16 g_B1 [(size_t)QKV_COLS * K3_1];
__device__ __align__(256) __nv_bfloat16 g_A2 [(size_t)M_TOTAL * K3_2];
__device__ __align__(256) __nv_bfloat16 g_B2 [(size_t)OUT_COLS * K3_2];

// ============================ PTX helpers ==================================
__device__ __forceinline__ uint32_t smem_u32(const void* p) {
    uint32_t a;
    asm("{ .reg .u64 t; cvta.to.shared.u64 t, %1; cvt.u32.u64 %0, t; }"
        : "=r"(a) : "l"(p));
    return a;
}
#define CP16(s, g) \
    asm volatile("cp.async.ca.shared.global [%0], [%1], 16;" :: "r"(s), "l"(g) : "memory")
#define CP_COMMIT() asm volatile("cp.async.commit_group;" ::: "memory")
template<int N> __device__ __forceinline__ void cp_wait() {
    asm volatile("cp.async.wait_group %0;" :: "n"(N) : "memory");
}

__device__ __forceinline__ void ldm_x4(uint32_t* r, uint32_t addr) {
    asm volatile("ldmatrix.sync.aligned.m8n8.x4.shared.b16 {%0,%1,%2,%3}, [%4];"
                 : "=r"(r[0]), "=r"(r[1]), "=r"(r[2]), "=r"(r[3]) : "r"(addr));
}
__device__ __forceinline__ void mma_bf16(float* c, const uint32_t* a,
                                         uint32_t b0, uint32_t b1) {
    asm volatile(
        "mma.sync.aligned.m16n8k16.row.col.f32.bf16.bf16.f32 "
        "{%0,%1,%2,%3}, {%4,%5,%6,%7}, {%8,%9}, {%0,%1,%2,%3};"
        : "+f"(c[0]), "+f"(c[1]), "+f"(c[2]), "+f"(c[3])
        : "r"(a[0]), "r"(a[1]), "r"(a[2]), "r"(a[3]), "r"(b0), "r"(b1));
}

// ============================ split kernel =================================
// fp32 [rows,K] -> bf16 [rows,3K].  MODE 0 (A): [hi|lo|hi];  MODE 1 (B): [hi|hi|lo].
template<int MODE>
__global__ void split3_kernel(const float* __restrict__ X,
                              __nv_bfloat16* __restrict__ Y,
                              int K, int K3, long long n4)
{
    long long i = (long long)blockIdx.x * blockDim.x + threadIdx.x;
    if (i >= n4) return;
    long long e = i * 4;
    long long row = e / K;
    int col = (int)(e - row * K);
    float4 x = *reinterpret_cast<const float4*>(X + e);

    union { __nv_bfloat16 b[4]; uint2 u; } hi, lo;
    hi.b[0] = __float2bfloat16(x.x); hi.b[1] = __float2bfloat16(x.y);
    hi.b[2] = __float2bfloat16(x.z); hi.b[3] = __float2bfloat16(x.w);
    lo.b[0] = __float2bfloat16(x.x - __bfloat162float(hi.b[0]));
    lo.b[1] = __float2bfloat16(x.y - __bfloat162float(hi.b[1]));
    lo.b[2] = __float2bfloat16(x.z - __bfloat162float(hi.b[2]));
    lo.b[3] = __float2bfloat16(x.w - __bfloat162float(hi.b[3]));

    __nv_bfloat16* yb = Y + row * K3 + col;
    *reinterpret_cast<uint2*>(yb) = hi.u;
    if (MODE == 0) {
        *reinterpret_cast<uint2*>(yb + K)     = lo.u;
        *reinterpret_cast<uint2*>(yb + 2 * K) = hi.u;
    } else {
        *reinterpret_cast<uint2*>(yb + K)     = hi.u;
        *reinterpret_cast<uint2*>(yb + 2 * K) = lo.u;
    }
}

// ============================ mma GEMM =====================================
// C[M,N] = A[M,K3] * B[N,K3]^T + bias[N].  bf16 in, fp32 out.
// 128 thr = 4 warps (2 CTAs/SM), warp tile WM x WN, ST-stage cp.async pipe.
template<int BM, int BN, int WM, int WN>
__global__ __launch_bounds__(128, 2)
void gemm_mma(const __nv_bfloat16* __restrict__ A,
              const __nv_bfloat16* __restrict__ B,
              const float* __restrict__ bias,
              float* __restrict__ C, int N, int K3)
{
    constexpr int NT   = 128;
    constexpr int BK   = 32;
    constexpr int LDK  = BK + 8;           // 80B row stride: ldmatrix bank-clean
    constexpr int ST   = 4;                // pipeline stages
    constexpr int MW   = BM / WM;          // warps along m
    constexpr int MT   = WM / 16;          // 16-row tiles per warp
    constexpr int NF   = WN / 8;           // n8 fragments per warp
    constexpr int NTL  = WN / 16;          // ldmatrix x4 B loads per warp
    constexpr int CA   = BM * (BK / 8) / NT;
    constexpr int CB   = BN * (BK / 8) / NT;
    static_assert(MW * (BN / WN) == 4, "4 warps");
    static_assert(CA >= 1 && CB >= 1, "tile loads");

    extern __shared__ __align__(16) char dyn[];
    __nv_bfloat16* sAp = reinterpret_cast<__nv_bfloat16*>(dyn);
    __nv_bfloat16* sBp = sAp + (size_t)ST * BM * LDK;
    const uint32_t uA = smem_u32(sAp);
    const uint32_t uB = smem_u32(sBp);

    const int tid  = threadIdx.x;
    const int wid  = tid >> 5;
    const int lane = tid & 31;
    const int bm   = blockIdx.y * BM;
    const int bn   = blockIdx.x * BN;
    const int wm   = (wid % MW) * WM;
    const int wn   = (wid / MW) * WN;

    // ldmatrix lane coordinates
    const int sel = lane >> 3, r8 = lane & 7;
    const int ar = wm + (sel & 1) * 8 + r8;      // A: (m8, k8) tile order
    const int ac = (sel >> 1) * 8;
    const int br = wn + (sel >> 1) * 8 + r8;     // B: (k8, n8) tile order
    const int bc = (sel & 1) * 8;

    float acc[MT][NF][4];
#pragma unroll
    for (int i = 0; i < MT; ++i)
#pragma unroll
        for (int j = 0; j < NF; ++j)
#pragma unroll
            for (int q = 0; q < 4; ++q) acc[i][j][q] = 0.f;

    const int NC = K3 / BK;

    auto load_stage = [&](int ci, int s) {
        const size_t k0 = (size_t)ci * BK;
#pragma unroll
        for (int i = 0; i < CA; ++i) {
            int ch = tid + i * NT;
            int rr = ch >> 2;                    // BK/8 = 4 chunks per row
            int cc = (ch & 3) * 8;
            const void* g = A + (size_t)(bm + rr) * K3 + k0 + cc;
            uint32_t sa = uA + (uint32_t)(((s * BM + rr) * LDK + cc) * 2);
            CP16(sa, g);
        }
#pragma unroll
        for (int i = 0; i < CB; ++i) {
            int ch = tid + i * NT;
            int rr = ch >> 2;
            int cc = (ch & 3) * 8;
            const void* g = B + (size_t)(bn + rr) * K3 + k0 + cc;
            uint32_t sb = uB + (uint32_t)(((s * BN + rr) * LDK + cc) * 2);
            CP16(sb, g);
        }
        CP_COMMIT();
    };

    // Prologue: ST-1 stages in flight.
#pragma unroll
    for (int p = 0; p < ST - 1; ++p) load_stage(p, p);

    for (int ci = 0; ci < NC; ++ci) {
        const int s = ci % ST;
        if (ci + ST - 1 < NC) cp_wait<ST - 2>();   // chunk ci landed
        else                  cp_wait<0>();        // tail drain
        __syncthreads();                           // fences slot reuse too

        if (ci + ST - 1 < NC) load_stage(ci + ST - 1, (ci + ST - 1) % ST);

#pragma unroll
        for (int ks = 0; ks < BK / 16; ++ks) {
            uint32_t afr[MT][4], bfr[NTL][4];
#pragma unroll
            for (int mt = 0; mt < MT; ++mt)
                ldm_x4(afr[mt], uA + (uint32_t)(((s * BM + ar + mt * 16) * LDK
                                                 + ac + ks * 16) * 2));
#pragma unroll
            for (int nt = 0; nt < NTL; ++nt)
                ldm_x4(bfr[nt], uB + (uint32_t)(((s * BN + br + nt * 16) * LDK
                                                 + bc + ks * 16) * 2));
#pragma unroll
            for (int mt = 0; mt < MT; ++mt)
#pragma unroll
                for (int nf = 0; nf < NF; ++nf) {
                    const uint32_t* bp = bfr[nf >> 1];
                    if (nf & 1) mma_bf16(acc[mt][nf], afr[mt], bp[2], bp[3]);
                    else        mma_bf16(acc[mt][nf], afr[mt], bp[0], bp[1]);
                }
        }
    }

    // Epilogue: bias + store (float2 per fragment row)
    const int g  = lane >> 2;
    const int t2 = (lane & 3) * 2;
#pragma unroll
    for (int mt = 0; mt < MT; ++mt) {
        int row0 = bm + wm + mt * 16 + g;
#pragma unroll
        for (int nf = 0; nf < NF; ++nf) {
            int col = bn + wn + nf * 8 + t2;
            float bx = __ldg(&bias[col]), by = __ldg(&bias[col + 1]);
            float2 v0 = make_float2(acc[mt][nf][0] + bx, acc[mt][nf][1] + by);
            float2 v1 = make_float2(acc[mt][nf][2] + bx, acc[mt][nf][3] + by);
            *reinterpret_cast<float2*>(&C[(size_t)row0 * N + col])       = v0;
            *reinterpret_cast<float2*>(&C[(size_t)(row0 + 8) * N + col]) = v1;
        }
    }
}

// ============================ attention ====================================
// Emits ctx directly as bf16 3-split rows of g_A2: [hi | lo | hi] over K=1024.
__global__ __launch_bounds__(256)
void attn_kernel(const float* __restrict__ qkv,
                 const float* __restrict__ biases,     // [8,49]
                 const int*   __restrict__ bias_idxs,  // [49*49] i32 (or i64 words)
                 __nv_bfloat16* __restrict__ A2)       // [M, 3072]
{
    const int b = blockIdx.x >> 3;
    const int h = blockIdx.x & 7;
    const int tid = threadIdx.x;

    __shared__ __align__(16) float vs[SEQ][128];
    __shared__ __align__(16) float qs[SEQ][33];
    __shared__ __align__(16) float ks[SEQ][33];
    __shared__ __align__(16) float sc[SEQ][SEQ];
    __shared__ __align__(16) float bias_s[SEQ];

    const bool idx64 = (__ldg(&bias_idxs[1]) == 0);

    const float* base = qkv + (size_t)b * (SEQ * QKV_COLS) + h * 192;
    for (int i = tid; i < SEQ * 192; i += 256) {
        int s = i / 192, c = i - s * 192;
        float val = base[(size_t)s * QKV_COLS + c];
        if (c < 32)       qs[s][c]       = val;
        else if (c < 64)  ks[s][c - 32]  = val;
        else              vs[s][c - 64]  = val;
    }
    if (tid < SEQ) bias_s[tid] = biases[h * SEQ + tid];
    __syncthreads();

    const float scale = 0.17677669529663687f;   // 32^-0.5
    for (int idx = tid; idx < SEQ * SEQ; idx += 256) {
        int qi = idx / SEQ, kj = idx - qi * SEQ;
        float acc = 0.f;
#pragma unroll
        for (int d = 0; d < 32; ++d) acc = fmaf(qs[qi][d], ks[kj][d], acc);
        int bidx = idx64 ? __ldg(&bias_idxs[2 * idx]) : __ldg(&bias_idxs[idx]);
        sc[qi][kj] = acc * scale + bias_s[bidx];
    }
    __syncthreads();

    if (tid < SEQ) {
        float m = -3.4e38f;
#pragma unroll 7
        for (int j = 0; j < SEQ; ++j) m = fmaxf(m, sc[tid][j]);
        float sum = 0.f;
        for (int j = 0; j < SEQ; ++j) {
            float e = expf(sc[tid][j] - m);
            sc[tid][j] = e;
            sum += e;
        }
        float inv = 1.f / sum;
        for (int j = 0; j < SEQ; ++j) sc[tid][j] *= inv;
    }
    __syncthreads();

    __nv_bfloat16* obase = A2 + (size_t)(b * SEQ) * K3_2 + h * 128;
    for (int u = tid; u < SEQ * 32; u += 256) {
        int qi = u >> 5;
        int d  = (u & 31) * 4;
        float4 acc = make_float4(0.f, 0.f, 0.f, 0.f);
#pragma unroll
        for (int j = 0; j < SEQ; ++j) {
            float p = sc[qi][j];
            float4 vv = *reinterpret_cast<const float4*>(&vs[j][d]);
            acc.x = fmaf(p, vv.x, acc.x);
            acc.y = fmaf(p, vv.y, acc.y);
            acc.z = fmaf(p, vv.z, acc.z);
            acc.w = fmaf(p, vv.w, acc.w);
        }
        union { __nv_bfloat16 bb[4]; uint2 u2; } hi, lo;
        hi.bb[0] = __float2bfloat16(acc.x); hi.bb[1] = __float2bfloat16(acc.y);
        hi.bb[2] = __float2bfloat16(acc.z); hi.bb[3] = __float2bfloat16(acc.w);
        lo.bb[0] = __float2bfloat16(acc.x - __bfloat162float(hi.bb[0]));
        lo.bb[1] = __float2bfloat16(acc.y - __bfloat162float(hi.bb[1]));
        lo.bb[2] = __float2bfloat16(acc.z - __bfloat162float(hi.bb[2]));
        lo.bb[3] = __float2bfloat16(acc.w - __bfloat162float(hi.bb[3]));
        __nv_bfloat16* orow = obase + (size_t)qi * K3_2 + d;
        *reinterpret_cast<uint2*>(orow)                = hi.u2;   // hi
        *reinterpret_cast<uint2*>(orow + CTX_COLS)     = lo.u2;   // lo
        *reinterpret_cast<uint2*>(orow + 2 * CTX_COLS) = hi.u2;   // hi
    }
}

// ============================ launch =======================================
extern "C" void kernel_launch(void* const* d_in, const int* in_sizes, int n_in,
                              void* d_out, int out_size)
{
    const float* hidden = (const float*)d_in[0];   // [2048,49,448]
    const float* qkv_w  = (const float*)d_in[1];   // [1536,448]
    const float* qkv_b  = (const float*)d_in[2];   // [1536]
    const float* proj_w = (const float*)d_in[3];   // [448,1024]
    const float* proj_b = (const float*)d_in[4];   // [448]
    const float* att_b  = (const float*)d_in[5];   // [8,49]
    const int*   idxs   = (const int*)d_in[6];     // [49,49]
    float* out = (float*)d_out;                    // [2048,49,448] fp32

    float* qkv; __nv_bfloat16 *A1, *B1, *A2, *B2;
    cudaGetSymbolAddress((void**)&qkv, g_qkv);
    cudaGetSymbolAddress((void**)&A1,  g_A1);
    cudaGetSymbolAddress((void**)&B1,  g_B1);
    cudaGetSymbolAddress((void**)&A2,  g_A2);
    cudaGetSymbolAddress((void**)&B2,  g_B2);

    // 4 stages * (BM + BN) rows * 80 B/row
    const int DYN1 = 4 * (128 + 128) * 80;   // 81920
    const int DYN2 = 4 * (128 + 64) * 80;    // 61440
    cudaFuncSetAttribute((const void*)gemm_mma<128, 128, 64, 64>,
                         cudaFuncAttributeMaxDynamicSharedMemorySize, DYN1);
    cudaFuncSetAttribute((const void*)gemm_mma<128, 64, 64, 32>,
                         cudaFuncAttributeMaxDynamicSharedMemorySize, DYN2);

    // splits for GEMM1 inputs (+ proj_w up front)
    {
        long long n4 = (long long)M_TOTAL * IN_COLS / 4;
        split3_kernel<0><<<(unsigned)((n4 + 255) / 256), 256>>>(hidden, A1, IN_COLS, K3_1, n4);
    }
    {
        long long n4 = (long long)QKV_COLS * IN_COLS / 4;
        split3_kernel<1><<<(unsigned)((n4 + 255) / 256), 256>>>(qkv_w, B1, IN_COLS, K3_1, n4);
    }
    {
        long long n4 = (long long)OUT_COLS * CTX_COLS / 4;
        split3_kernel<1><<<(unsigned)((n4 + 255) / 256), 256>>>(proj_w, B2, CTX_COLS, K3_2, n4);
    }

    // GEMM1: qkv = A1 @ B1^T + qkv_b   (M=100352, N=1536, K'=1344)
    {
        dim3 grid(QKV_COLS / 128, M_TOTAL / 128);
        gemm_mma<128, 128, 64, 64><<<grid, 128, DYN1>>>(A1, B1, qkv_b, qkv, QKV_COLS, K3_1);
    }

    // Attention (writes bf16-split ctx into A2)
    attn_kernel<<<2048 * NHEADS, 256>>>(qkv, att_b, idxs, A2);

    // GEMM2: out = A2 @ B2^T + proj_b  (M=100352, N=448, K'=3072)
    {
        dim3 grid(OUT_COLS / 64, M_TOTAL / 128);
        gemm_mma<128, 64, 64, 32><<<grid, 128, DYN2>>>(A2, B2, proj_b, out, OUT_COLS, K3_2);
    }
}